// round 1
// baseline (speedup 1.0000x reference)
#include <cuda_runtime.h>
#include <cstdint>

// ---------------------------------------------------------------------------
// Problem constants
// ---------------------------------------------------------------------------
// B=64, T=4, N=6, IMG=128, CIN=3, VE=64, D=256, P=4, num_rollouts=8
#define NB 64
#define NT 4
#define NN 6
#define NBT 256            // B*T
#define NROI 1536          // B*T*N
#define NROW 384           // B*N   (rows of a per-timestep state)
#define ND 256
#define SD (NROW*ND)       // 98304, one state buffer
#define NROLL 8

// ---------------------------------------------------------------------------
// Device scratch (static: no allocation anywhere)
// ---------------------------------------------------------------------------
__device__ float g_f1[(size_t)NBT * 64 * 64 * 64];   // conv1 out (256,64,64,64)
__device__ float g_f2[(size_t)NBT * 64 * 32 * 32];   // conv2 out (256,64,32,32)
__device__ float g_pool [NROI * 1024];
__device__ float g_obj  [NROI * ND];
__device__ float g_emb1 [NROI * ND];
__device__ float g_emb2 [NROI * ND];
__device__ float g_sttmp[NROI * ND];                 // red output, (B,T,N,D) order
__device__ float g_O[4 * SD];                        // initial states per t (t, b*6+n, d)
__device__ float g_P[8 * SD];                        // produced states per rollout
__device__ float g_selfd[4 * SD];
__device__ float g_u[4 * SD];
__device__ float g_v[4 * SD];
__device__ float g_t[4 * SD];
__device__ float g_a[4 * SD];
__device__ float g_cs[NROW * 1024];                  // concat of 4 cs, column-blocked
__device__ float g_r[NROW];                          // radii (b*6+n)

// ---------------------------------------------------------------------------
// r kernel: r[b,n] = mean_t ((roi4-roi2)/2 + (roi3-roi1)/2)/2
// ---------------------------------------------------------------------------
__global__ void r_kernel(const float* __restrict__ rois) {
    int i = blockIdx.x * 128 + threadIdx.x;
    if (i >= NROW) return;
    int b = i / NN, n = i % NN;
    float s = 0.f;
    for (int t = 0; t < NT; ++t) {
        const float* ro = rois + (size_t)(((b * NT + t) * NN) + n) * 5;
        s += ((ro[4] - ro[2]) * 0.5f + (ro[3] - ro[1]) * 0.5f) * 0.5f;
    }
    g_r[i] = s * 0.25f;
}

// ---------------------------------------------------------------------------
// conv1: (256,3,128,128) -> relu -> (256,64,64,64), 3x3 stride 2, SAME (pad_lo=0)
// grid (oy=64, bt=256), block 256 = 16 oxt x 16 cot, micro 4co x 4ox
// ---------------------------------------------------------------------------
__global__ void conv1_kernel(const float* __restrict__ x,
                             const float* __restrict__ w1,
                             const float* __restrict__ b1) {
    int oy = blockIdx.x, bt = blockIdx.y;
    __shared__ float ins[3 * 3 * 132];   // [ci][kh][132]; ix up to 128 (pad=0)
    __shared__ float ws[27 * 64];        // [off(=ci*9+kh*3+kw)][co]
    __shared__ float bs[64];
    int tid = threadIdx.x;
    for (int i = tid; i < 3 * 3 * 132; i += 256) {
        int ci = i / 396, rem = i % 396, kh = rem / 132, ix = rem % 132;
        int iy = 2 * oy + kh;
        float v = 0.f;
        if (iy < 128 && ix < 128)
            v = x[(((size_t)bt * 3 + ci) * 128 + iy) * 128 + ix];
        ins[i] = v;
    }
    for (int i = tid; i < 1728; i += 256) {
        int co = i / 27, off = i % 27;
        ws[off * 64 + co] = w1[i];
    }
    if (tid < 64) bs[tid] = b1[tid];
    __syncthreads();

    int oxt = tid & 15, cot = tid >> 4;
    int ox0 = oxt * 4, co0 = cot * 4;
    float acc[4][4] = {};
#pragma unroll
    for (int ci = 0; ci < 3; ++ci)
#pragma unroll
        for (int kh = 0; kh < 3; ++kh) {
            const float* ip = &ins[(ci * 3 + kh) * 132 + ox0 * 2];
            float iv[9];
#pragma unroll
            for (int j = 0; j < 9; ++j) iv[j] = ip[j];
#pragma unroll
            for (int kw = 0; kw < 3; ++kw) {
                float4 w = *(const float4*)&ws[(ci * 9 + kh * 3 + kw) * 64 + co0];
#pragma unroll
                for (int dx = 0; dx < 4; ++dx) {
                    float v = iv[2 * dx + kw];
                    acc[0][dx] += w.x * v;
                    acc[1][dx] += w.y * v;
                    acc[2][dx] += w.z * v;
                    acc[3][dx] += w.w * v;
                }
            }
        }
#pragma unroll
    for (int dc = 0; dc < 4; ++dc) {
        float bb = bs[co0 + dc];
        float4 o;
        o.x = fmaxf(acc[dc][0] + bb, 0.f);
        o.y = fmaxf(acc[dc][1] + bb, 0.f);
        o.z = fmaxf(acc[dc][2] + bb, 0.f);
        o.w = fmaxf(acc[dc][3] + bb, 0.f);
        *(float4*)&g_f1[(((size_t)bt * 64 + co0 + dc) * 64 + oy) * 64 + ox0] = o;
    }
}

// ---------------------------------------------------------------------------
// conv2: (256,64,64,64) -> relu -> (256,64,32,32), 3x3 stride 2, SAME (pad_lo=0)
// grid (oy=32, bt=256), block 128 = 8 oxt x 16 cot, micro 4co x 4ox, ci chunks of 8
// ---------------------------------------------------------------------------
__global__ void conv2_kernel(const float* __restrict__ w2,
                             const float* __restrict__ b2) {
    int oy = blockIdx.x, bt = blockIdx.y;
    __shared__ float ins[8 * 3 * 68];    // [ci][kh][68]; ix up to 64 (pad)
    __shared__ float ws[8 * 9 * 64];     // [off(=ci*9+kh*3+kw)][co]
    int tid = threadIdx.x;
    int oxt = tid & 7, cot = tid >> 3;
    int ox0 = oxt * 4, co0 = cot * 4;
    float acc[4][4] = {};
#pragma unroll 1
    for (int cc = 0; cc < 8; ++cc) {
        __syncthreads();
        for (int i = tid; i < 8 * 3 * 68; i += 128) {
            int ci = i / 204, rem = i % 204, row = rem / 68, ix = rem % 68;
            int iy = 2 * oy + row;
            int cig = cc * 8 + ci;
            float v = 0.f;
            if (ix < 64 && iy < 64)
                v = g_f1[(((size_t)bt * 64 + cig) * 64 + iy) * 64 + ix];
            ins[i] = v;
        }
        for (int i = tid; i < 8 * 72; i += 128) {   // 576 elements... per co
        }
        for (int i = tid; i < 64 * 72; i += 128) {
            int co = i / 72, off = i % 72;
            ws[off * 64 + co] = w2[(size_t)co * 576 + cc * 72 + off];
        }
        __syncthreads();
#pragma unroll
        for (int ci = 0; ci < 8; ++ci)
#pragma unroll
            for (int kh = 0; kh < 3; ++kh) {
                const float* ip = &ins[(ci * 3 + kh) * 68 + ox0 * 2];
                float iv[9];
#pragma unroll
                for (int j = 0; j < 9; ++j) iv[j] = ip[j];
#pragma unroll
                for (int kw = 0; kw < 3; ++kw) {
                    float4 w = *(const float4*)&ws[((ci * 3 + kh) * 3 + kw) * 64 + co0];
#pragma unroll
                    for (int dx = 0; dx < 4; ++dx) {
                        float v = iv[2 * dx + kw];
                        acc[0][dx] += w.x * v;
                        acc[1][dx] += w.y * v;
                        acc[2][dx] += w.z * v;
                        acc[3][dx] += w.w * v;
                    }
                }
            }
    }
#pragma unroll
    for (int dc = 0; dc < 4; ++dc) {
        float bb = b2[co0 + dc];
        float4 o;
        o.x = fmaxf(acc[dc][0] + bb, 0.f);
        o.y = fmaxf(acc[dc][1] + bb, 0.f);
        o.z = fmaxf(acc[dc][2] + bb, 0.f);
        o.w = fmaxf(acc[dc][3] + bb, 0.f);
        *(float4*)&g_f2[(((size_t)bt * 64 + co0 + dc) * 32 + oy) * 32 + ox0] = o;
    }
}

// ---------------------------------------------------------------------------
// roi_align: feat (256,64,32,32) + rois (1536,5) -> pool (1536, 64*4*4)
// ---------------------------------------------------------------------------
__global__ void roi_kernel(const float* __restrict__ rois) {
    int r = blockIdx.x;
    __shared__ float ro[5];
    if (threadIdx.x < 5) ro[threadIdx.x] = rois[(size_t)r * 5 + threadIdx.x];
    __syncthreads();
    int bt = (int)ro[0];
    float x1 = ro[1] * 0.25f, y1 = ro[2] * 0.25f;
    float x2 = ro[3] * 0.25f, y2 = ro[4] * 0.25f;
    float bw = fmaxf(x2 - x1, 1.f) * 0.25f;
    float bh = fmaxf(y2 - y1, 1.f) * 0.25f;
    for (int idx = threadIdx.x; idx < 1024; idx += 256) {
        int c = idx >> 4, py = (idx >> 2) & 3, px = idx & 3;
        float sx = x1 + bw * (px + 0.5f);
        float sy = y1 + bh * (py + 0.5f);
        float x0f = fminf(fmaxf(floorf(sx), 0.f), 31.f);
        float y0f = fminf(fmaxf(floorf(sy), 0.f), 31.f);
        float lx = fminf(fmaxf(sx - x0f, 0.f), 1.f);
        float ly = fminf(fmaxf(sy - y0f, 0.f), 1.f);
        int x0 = (int)x0f, y0 = (int)y0f;
        int x1i = min(x0 + 1, 31), y1i = min(y0 + 1, 31);
        const float* f = &g_f2[((size_t)bt * 64 + c) * 1024];
        float v00 = f[y0 * 32 + x0];
        float v01 = f[y0 * 32 + x1i];
        float v10 = f[y1i * 32 + x0];
        float v11 = f[y1i * 32 + x1i];
        float val = v00 * (1.f - ly) * (1.f - lx) + v01 * (1.f - ly) * lx +
                    v10 * ly * (1.f - lx) + v11 * ly * lx;
        g_pool[(size_t)r * 1024 + idx] = val;
    }
}

// ---------------------------------------------------------------------------
// emb0: relu(src_coor @ fc0c_w.T + b), K=2 (too small for the tiled GEMM)
// ---------------------------------------------------------------------------
__global__ void emb0_kernel(const float* __restrict__ sc,
                            const float* __restrict__ w,
                            const float* __restrict__ b) {
    int row = blockIdx.x, c = threadIdx.x;
    float x0 = sc[(size_t)row * 2], x1 = sc[(size_t)row * 2 + 1];
    float e = fmaf(w[c * 2], x0, fmaf(w[c * 2 + 1], x1, b[c]));
    g_emb1[(size_t)row * ND + c] = fmaxf(e, 0.f);
}

// ---------------------------------------------------------------------------
// rearrange red output (B,T,N,D) -> g_O[t][b*6+n][d]
// ---------------------------------------------------------------------------
__global__ void rearr_kernel() {
    int i = blockIdx.x * 256 + threadIdx.x;     // < 1536*256
    int d = i & 255;
    int m = i >> 8;
    int n = m % NN;
    int t = (m / NN) % NT;
    int b = m / (NN * NT);
    g_O[((size_t)t * NROW + b * NN + n) * ND + d] = g_sttmp[i];
}

// ---------------------------------------------------------------------------
// Generic NT GEMM: C[m,n] = act( sum_k A(m,k) * W[n, k] + bias[n] )
//   A split into A1 (cols 0..K1) and A2 (cols K1..K1+K2) for concat inputs.
//   Batched over blockIdx.z via pointer tables. All dims multiples of tiles.
// ---------------------------------------------------------------------------
struct GemmArgs {
    const float* A1[12];
    const float* A2[12];
    const float* W[12];
    const float* Bias[12];
    float*       C[12];
    int          ldw[12];
    int lda1, lda2, ldc, M, N, K1, K2, relu;
};

__global__ void gemm_nt_kernel(GemmArgs g) {
    const int z = blockIdx.z;
    const float* __restrict__ A1 = g.A1[z];
    const float* __restrict__ A2 = g.A2[z];
    const float* __restrict__ W  = g.W[z];
    const float* __restrict__ Bv = g.Bias[z];
    float* __restrict__ C = g.C[z];
    const int ldw = g.ldw[z];
    const int m0 = blockIdx.x * 64, n0 = blockIdx.y * 64;
    __shared__ float As[16 * 68];
    __shared__ float Ws[16 * 68];
    const int tid = threadIdx.x;
    const int lr = tid >> 2, lc = (tid & 3) * 4;
    const int ty = tid >> 4, tx = tid & 15;
    float acc[4][4] = {};
    const int K = g.K1 + g.K2;
    for (int kk = 0; kk < K; kk += 16) {
        int col = kk + lc;
        const float* ap;
        if (col < g.K1) ap = A1 + (size_t)(m0 + lr) * g.lda1 + col;
        else            ap = A2 + (size_t)(m0 + lr) * g.lda2 + (col - g.K1);
        float4 av = *(const float4*)ap;
        float4 wv = *(const float4*)(W + (size_t)(n0 + lr) * ldw + col);
        As[(lc + 0) * 68 + lr] = av.x; As[(lc + 1) * 68 + lr] = av.y;
        As[(lc + 2) * 68 + lr] = av.z; As[(lc + 3) * 68 + lr] = av.w;
        Ws[(lc + 0) * 68 + lr] = wv.x; Ws[(lc + 1) * 68 + lr] = wv.y;
        Ws[(lc + 2) * 68 + lr] = wv.z; Ws[(lc + 3) * 68 + lr] = wv.w;
        __syncthreads();
#pragma unroll
        for (int k = 0; k < 16; ++k) {
            float4 a = *(const float4*)&As[k * 68 + ty * 4];
            float4 b = *(const float4*)&Ws[k * 68 + tx * 4];
            acc[0][0] += a.x * b.x; acc[0][1] += a.x * b.y; acc[0][2] += a.x * b.z; acc[0][3] += a.x * b.w;
            acc[1][0] += a.y * b.x; acc[1][1] += a.y * b.y; acc[1][2] += a.y * b.z; acc[1][3] += a.y * b.w;
            acc[2][0] += a.z * b.x; acc[2][1] += a.z * b.y; acc[2][2] += a.z * b.z; acc[2][3] += a.z * b.w;
            acc[3][0] += a.w * b.x; acc[3][1] += a.w * b.y; acc[3][2] += a.w * b.z; acc[3][3] += a.w * b.w;
        }
        __syncthreads();
    }
    int n = n0 + tx * 4;
    float b0 = 0.f, b1 = 0.f, b2 = 0.f, b3 = 0.f;
    if (Bv) { b0 = Bv[n]; b1 = Bv[n + 1]; b2 = Bv[n + 2]; b3 = Bv[n + 3]; }
#pragma unroll
    for (int i = 0; i < 4; ++i) {
        float4 o;
        o.x = acc[i][0] + b0; o.y = acc[i][1] + b1;
        o.z = acc[i][2] + b2; o.w = acc[i][3] + b3;
        if (g.relu) {
            o.x = fmaxf(o.x, 0.f); o.y = fmaxf(o.y, 0.f);
            o.z = fmaxf(o.z, 0.f); o.w = fmaxf(o.w, 0.f);
        }
        *(float4*)(C + (size_t)(m0 + ty * 4 + i) * g.ldc + n) = o;
    }
}

// ---------------------------------------------------------------------------
// masked relational sum:
//   t[k][b*6+i][d] = selfd + cnt_i*(u_i[d] + rb_k[d]) + sum_j mask_ij * v_j[d]
// grid (b=64, k=4), block 256 (= d)
// ---------------------------------------------------------------------------
struct MaskArgs {
    const float* coor[4];
    int cbs[4];   // batch stride (elements)
    int cns[4];   // n stride (elements)
    const float* relb;  // (4,256)
};

__global__ void mask_relsum_kernel(MaskArgs ma) {
    int b = blockIdx.x, k = blockIdx.y;
    __shared__ float cx[NN], cy[NN], rr[NN], cnt[NN];
    __shared__ int   mask[NN][NN];
    int tid = threadIdx.x;
    if (tid < NN) {
        const float* cp = ma.coor[k] + (size_t)b * ma.cbs[k] + tid * ma.cns[k];
        cx[tid] = cp[0];
        cy[tid] = cp[1];
        rr[tid] = g_r[b * NN + tid];
    }
    __syncthreads();
    if (tid < NN * NN) {
        int i = tid / NN, j = tid % NN;
        float dx = cx[i] - cx[j], dy = cy[i] - cy[j];
        float dist = sqrtf(dx * dx + dy * dy);
        mask[i][j] = (i != j) && (dist <= rr[i] + rr[j]);
    }
    __syncthreads();
    if (tid < NN) {
        int c = 0;
        for (int j = 0; j < NN; ++j) c += mask[tid][j];
        cnt[tid] = (float)c;
    }
    __syncthreads();
    int d = tid;
    float rb = ma.relb[k * ND + d];
    size_t base = (size_t)k * SD + (size_t)b * NN * ND;
    float vv[NN];
#pragma unroll
    for (int j = 0; j < NN; ++j) vv[j] = g_v[base + j * ND + d];
#pragma unroll
    for (int i = 0; i < NN; ++i) {
        float acc = g_selfd[base + i * ND + d] + cnt[i] * (g_u[base + i * ND + d] + rb);
#pragma unroll
        for (int j = 0; j < NN; ++j)
            if (mask[i][j]) acc += vv[j];
        g_t[base + i * ND + d] = acc;
    }
}

// ---------------------------------------------------------------------------
// dec: bbox = s @ dec_w.T + dec_b, scatter into output (B, 8, N, 4)
// grid 384, block 32 (one warp per row)
// ---------------------------------------------------------------------------
__global__ void dec_kernel(const float* __restrict__ s,
                           const float* __restrict__ dw,
                           const float* __restrict__ db,
                           float* __restrict__ out, int it) {
    int row = blockIdx.x;
    int lane = threadIdx.x;
    const float* sp = s + (size_t)row * ND;
    float p0 = 0.f, p1 = 0.f, p2 = 0.f, p3 = 0.f;
    for (int k = lane; k < ND; k += 32) {
        float v = sp[k];
        p0 += v * dw[k];
        p1 += v * dw[256 + k];
        p2 += v * dw[512 + k];
        p3 += v * dw[768 + k];
    }
#pragma unroll
    for (int off = 16; off > 0; off >>= 1) {
        p0 += __shfl_down_sync(0xffffffffu, p0, off);
        p1 += __shfl_down_sync(0xffffffffu, p1, off);
        p2 += __shfl_down_sync(0xffffffffu, p2, off);
        p3 += __shfl_down_sync(0xffffffffu, p3, off);
    }
    if (lane == 0) {
        int b = row / NN, n = row % NN;
        float* o = out + (size_t)b * (NROLL * NN * 4) + it * (NN * 4) + n * 4;
        o[0] = p0 + db[0];
        o[1] = p1 + db[1];
        o[2] = p2 + db[2];
        o[3] = p3 + db[3];
    }
}

// ---------------------------------------------------------------------------
// Host launcher
// ---------------------------------------------------------------------------
static void launch_gemm(int numZ, int M, int N, int K1, int K2,
                        const float* const* A1, int lda1,
                        const float* const* A2, int lda2,
                        const float* const* W, const int* ldw,
                        const float* const* Bias,
                        float* const* C, int ldc, int relu) {
    GemmArgs ga;
    for (int z = 0; z < numZ; ++z) {
        ga.A1[z] = A1[z];
        ga.A2[z] = A2 ? A2[z] : A1[z];
        ga.W[z] = W[z];
        ga.Bias[z] = Bias ? Bias[z] : nullptr;
        ga.C[z] = C[z];
        ga.ldw[z] = ldw[z];
    }
    for (int z = numZ; z < 12; ++z) { ga.A1[z] = ga.A1[0]; ga.A2[z] = ga.A2[0]; ga.W[z] = ga.W[0]; ga.Bias[z] = nullptr; ga.C[z] = ga.C[0]; ga.ldw[z] = ga.ldw[0]; }
    ga.lda1 = lda1; ga.lda2 = lda2; ga.ldc = ldc;
    ga.M = M; ga.N = N; ga.K1 = K1; ga.K2 = K2; ga.relu = relu;
    dim3 grid(M / 64, N / 64, numZ);
    gemm_nt_kernel<<<grid, 256>>>(ga);
}

extern "C" void kernel_launch(void* const* d_in, const int* in_sizes, int n_in,
                              void* d_out, int out_size) {
    const float* x       = (const float*)d_in[0];
    const float* rois    = (const float*)d_in[1];
    const float* src     = (const float*)d_in[2];
    const float* w_conv1 = (const float*)d_in[3];
    const float* b_conv1 = (const float*)d_in[4];
    const float* w_conv2 = (const float*)d_in[5];
    const float* b_conv2 = (const float*)d_in[6];
    const float* fc0_w   = (const float*)d_in[7];
    const float* fc0_b   = (const float*)d_in[8];
    const float* fc0c_w  = (const float*)d_in[9];
    const float* fc0c_b  = (const float*)d_in[10];
    const float* fc1c_w  = (const float*)d_in[11];
    const float* fc1c_b  = (const float*)d_in[12];
    const float* red_w   = (const float*)d_in[13];
    const float* red_b   = (const float*)d_in[14];
    const float* g_self_w = (const float*)d_in[15];
    const float* g_self_b = (const float*)d_in[16];
    const float* g_rel_w  = (const float*)d_in[17];
    const float* g_rel_b  = (const float*)d_in[18];
    const float* g_aff_w  = (const float*)d_in[19];
    const float* g_aff_b  = (const float*)d_in[20];
    const float* g_out_w  = (const float*)d_in[21];
    const float* g_out_b  = (const float*)d_in[22];
    const float* agg_w   = (const float*)d_in[23];
    const float* agg_b   = (const float*)d_in[24];
    const float* dec_w   = (const float*)d_in[25];
    const float* dec_b   = (const float*)d_in[26];
    float* outp = (float*)d_out;

    // scratch pointers
    float *pool, *obj, *emb1, *emb2, *sttmp, *O, *P, *selfd, *u, *v, *t, *a, *cs;
    cudaGetSymbolAddress((void**)&pool,  g_pool);
    cudaGetSymbolAddress((void**)&obj,   g_obj);
    cudaGetSymbolAddress((void**)&emb1,  g_emb1);
    cudaGetSymbolAddress((void**)&emb2,  g_emb2);
    cudaGetSymbolAddress((void**)&sttmp, g_sttmp);
    cudaGetSymbolAddress((void**)&O,     g_O);
    cudaGetSymbolAddress((void**)&P,     g_P);
    cudaGetSymbolAddress((void**)&selfd, g_selfd);
    cudaGetSymbolAddress((void**)&u,     g_u);
    cudaGetSymbolAddress((void**)&v,     g_v);
    cudaGetSymbolAddress((void**)&t,     g_t);
    cudaGetSymbolAddress((void**)&a,     g_a);
    cudaGetSymbolAddress((void**)&cs,    g_cs);

    // ---- preamble ----
    r_kernel<<<3, 128>>>(rois);
    conv1_kernel<<<dim3(64, NBT), 256>>>(x, w_conv1, b_conv1);
    conv2_kernel<<<dim3(32, NBT), 128>>>(w_conv2, b_conv2);
    roi_kernel<<<NROI, 256>>>(rois);
    emb0_kernel<<<NROI, 256>>>(src, fc0c_w, fc0c_b);

    {   // fc1c: emb2 = relu(emb1 @ fc1c_w.T + b)
        const float* A1[1] = { emb1 };
        const float* W[1] = { fc1c_w }; int ldw[1] = { 256 };
        const float* B[1] = { fc1c_b };
        float* C[1] = { emb2 };
        launch_gemm(1, NROI, ND, 256, 0, A1, 256, nullptr, 0, W, ldw, B, C, ND, 1);
    }
    {   // fc0: obj = relu(pool @ fc0_w.T + b)
        const float* A1[1] = { pool };
        const float* W[1] = { fc0_w }; int ldw[1] = { 1024 };
        const float* B[1] = { fc0_b };
        float* C[1] = { obj };
        launch_gemm(1, NROI, ND, 1024, 0, A1, 1024, nullptr, 0, W, ldw, B, C, ND, 1);
    }
    {   // red: sttmp = relu(concat(obj,emb2) @ red_w.T + b)
        const float* A1[1] = { obj };
        const float* A2[1] = { emb2 };
        const float* W[1] = { red_w }; int ldw[1] = { 512 };
        const float* B[1] = { red_b };
        float* C[1] = { sttmp };
        launch_gemm(1, NROI, ND, 256, 256, A1, 256, A2, 256, W, ldw, B, C, ND, 1);
    }
    rearr_kernel<<<NROI, 256>>>();

    // ---- rollouts ----
    for (int it = 0; it < NROLL; ++it) {
        const float* st[4];
        MaskArgs ma;
        for (int k = 0; k < 4; ++k) {
            int idx = it + k;
            st[k] = (idx < 4) ? (O + (size_t)idx * SD) : (P + (size_t)(idx - 4) * SD);
            if (idx < 4) {
                ma.coor[k] = src + idx * (NN * 2);
                ma.cbs[k] = NT * NN * 2;   // 48
                ma.cns[k] = 2;
            } else {
                ma.coor[k] = outp + (idx - 4) * (NN * 4) + 2;
                ma.cbs[k] = NROLL * NN * 4;  // 192
                ma.cns[k] = 4;
            }
        }
        ma.relb = g_rel_b;

        // self_d / u / v: 12-way batched GEMM (K=256, no relu)
        {
            const float* A1[12]; const float* W[12]; const float* B[12];
            float* C[12]; int ldw[12];
            for (int z = 0; z < 12; ++z) {
                int k = z & 3, kind = z >> 2;
                A1[z] = st[k];
                if (kind == 0) { W[z] = g_self_w + (size_t)k * 65536;       ldw[z] = 256; B[z] = g_self_b + k * 256; C[z] = selfd + (size_t)k * SD; }
                else if (kind == 1) { W[z] = g_rel_w + (size_t)k * 131072;  ldw[z] = 512; B[z] = nullptr; C[z] = u + (size_t)k * SD; }
                else { W[z] = g_rel_w + (size_t)k * 131072 + 256;           ldw[z] = 512; B[z] = nullptr; C[z] = v + (size_t)k * SD; }
            }
            launch_gemm(12, NROW, ND, 256, 0, A1, 256, nullptr, 0, W, ldw, B, C, ND, 0);
        }
        mask_relsum_kernel<<<dim3(NB, 4), 256>>>(ma);
        {   // aff: a = relu(t @ aff_w.T + b)
            const float* A1[4]; const float* W[4]; const float* B[4];
            float* C[4]; int ldw[4];
            for (int k = 0; k < 4; ++k) {
                A1[k] = t + (size_t)k * SD;
                W[k] = g_aff_w + (size_t)k * 65536; ldw[k] = 256;
                B[k] = g_aff_b + k * 256;
                C[k] = a + (size_t)k * SD;
            }
            launch_gemm(4, NROW, ND, 256, 0, A1, 256, nullptr, 0, W, ldw, B, C, ND, 1);
        }
        {   // out: cs_k = relu(concat(a, state) @ ow.T + b), written into column block k
            const float* A1[4]; const float* A2[4]; const float* W[4]; const float* B[4];
            float* C[4]; int ldw[4];
            for (int k = 0; k < 4; ++k) {
                A1[k] = a + (size_t)k * SD;
                A2[k] = st[k];
                W[k] = g_out_w + (size_t)k * 131072; ldw[k] = 512;
                B[k] = g_out_b + k * 256;
                C[k] = cs + k * 256;
            }
            launch_gemm(4, NROW, ND, 256, 256, A1, 256, A2, 256, W, ldw, B, C, 1024, 1);
        }
        {   // agg: s_new = cs @ agg_w.T + b (no relu)
            const float* A1[1] = { cs };
            const float* W[1] = { agg_w }; int ldw[1] = { 1024 };
            const float* B[1] = { agg_b };
            float* C[1] = { P + (size_t)it * SD };
            launch_gemm(1, NROW, ND, 1024, 0, A1, 1024, nullptr, 0, W, ldw, B, C, ND, 0);
        }
        dec_kernel<<<NROW, 32>>>(P + (size_t)it * SD, dec_w, dec_b, outp, it);
    }

    (void)in_sizes; (void)n_in; (void)out_size;
}